// round 4
// baseline (speedup 1.0000x reference)
#include <cuda_runtime.h>
#include <cuda_bf16.h>
#include <cstdint>

#define NN 20000
#define NE 640000
#define P_PATH 512
#define S_SUB 64
#define DHID 256

typedef unsigned long long ull;

// ---------------- scratch (static device globals; no allocation) ----------------
static __device__ float g_agg[NN * 128];
static __device__ float g_part[NN * 256];
static __device__ float g_h1[NN * 24];
static __device__ float g_h2[NN * 64];
static __device__ float g_h3[NN * 128];
static __device__ float g_h4[NN * 256];
static __device__ int g_deg[NN];
static __device__ int g_off[NN + 1];
static __device__ int g_cur[NN];
static __device__ int g_srcs[NE];
static __device__ float g_c[3 * 1024];
static __device__ float g_r0[3 * P_PATH * 256];
static __device__ float g_gates[3 * P_PATH * 1024];
static __device__ float g_q1[3 * P_PATH * 256];
static __device__ float g_r1[3 * P_PATH * 256];
static __device__ float g_xg[P_PATH];

__device__ __forceinline__ float sigm(float x) { return 1.f / (1.f + __expf(-x)); }

__device__ __forceinline__ void ffma2(ull& acc, ull a, ull b) {
    asm("fma.rn.f32x2 %0, %1, %2, %0;" : "+l"(acc) : "l"(a), "l"(b));
}
__device__ __forceinline__ float hsum2(ull v) {
    return __uint_as_float((unsigned)v) + __uint_as_float((unsigned)(v >> 32));
}

// ---------------- CSR build ----------------
__global__ void hist_kernel(const int* __restrict__ dst, int* __restrict__ deg, int E) {
    int e = blockIdx.x * blockDim.x + threadIdx.x;
    if (e < E) atomicAdd(&deg[dst[e]], 1);
}

__global__ void scan_kernel(const int* __restrict__ deg, int* __restrict__ off,
                            int* __restrict__ cur) {
    __shared__ int part[1024];
    int t = threadIdx.x;
    const int CH = (NN + 1023) / 1024;
    int start = t * CH;
    int end = min(start + CH, NN);
    int s = 0;
    for (int i = start; i < end; i++) s += deg[i];
    part[t] = s;
    __syncthreads();
    for (int o = 1; o < 1024; o <<= 1) {
        int v = (t >= o) ? part[t - o] : 0;
        __syncthreads();
        part[t] += v;
        __syncthreads();
    }
    int base = (t > 0) ? part[t - 1] : 0;
    for (int i = start; i < end; i++) {
        off[i] = base;
        cur[i] = base;
        base += deg[i];
    }
    if (t == 1023) off[NN] = part[1023];
}

__global__ void bucket_kernel(const int* __restrict__ src, const int* __restrict__ dst,
                              int* __restrict__ cur, int* __restrict__ srcs, int E) {
    int e = blockIdx.x * blockDim.x + threadIdx.x;
    if (e < E) {
        int p = atomicAdd(&cur[dst[e]], 1);
        srcs[p] = src[e];
    }
}

// ---------------- direct gather aggregation (large D) ----------------
template <int D>
__global__ void aggregate_k(const float* __restrict__ h, const int* __restrict__ off,
                            const int* __restrict__ srcs, float* __restrict__ outp) {
    constexpr int C = D / 4;
    int idx = blockIdx.x * blockDim.x + threadIdx.x;
    if (idx >= NN * C) return;
    int node = idx / C;
    int c = idx - node * C;
    const float4* hp = reinterpret_cast<const float4*>(h);
    float4 acc = hp[(size_t)node * C + c];
    int s0 = off[node], s1 = off[node + 1];
#pragma unroll 8
    for (int j = s0; j < s1; j++) {
        int s = __ldg(&srcs[j]);
        float4 v = hp[(size_t)s * C + c];
        acc.x += v.x;
        acc.y += v.y;
        acc.z += v.z;
        acc.w += v.w;
    }
    reinterpret_cast<float4*>(outp)[idx] = acc;
}

// ---------------- sliced aggregation (small D): NS partial sums per node ----------------
template <int D, int NS>
__global__ void aggregate_sliced(const float* __restrict__ h, const int* __restrict__ off,
                                 const int* __restrict__ srcs, float* __restrict__ part) {
    constexpr int C = D / 4;
    int idx = blockIdx.x * blockDim.x + threadIdx.x;
    if (idx >= NN * C * NS) return;
    int slice = idx / (NN * C);
    int rem = idx - slice * NN * C;
    int node = rem / C;
    int c = rem - node * C;
    const float4* hp = reinterpret_cast<const float4*>(h);
    int s0 = off[node], s1 = off[node + 1];
    int len = s1 - s0;
    int a = s0 + (len * slice) / NS;
    int b = s0 + (len * (slice + 1)) / NS;
    float4 acc = {0.f, 0.f, 0.f, 0.f};
#pragma unroll 4
    for (int j = a; j < b; j++) {
        int s = __ldg(&srcs[j]);
        float4 v = hp[(size_t)s * C + c];
        acc.x += v.x;
        acc.y += v.y;
        acc.z += v.z;
        acc.w += v.w;
    }
    reinterpret_cast<float4*>(part)[(size_t)slice * NN * C + (size_t)node * C + c] = acc;
}

// ---------------- GIN GEMM: out = relu(xin_sum @ W^T + b), f32x2 FMA ----------------
// If NSLICE>0: xin_sum[row] = xin[row] + sum_s part[s][row]. W: [N,K] row-major.
template <int K, int N, int NP, int T, int RPB, int NSLICE>
__global__ void gemm_relu(const float* __restrict__ xin, const float* __restrict__ part,
                          const float* __restrict__ W, const float* __restrict__ b,
                          float* __restrict__ out, int nrows) {
    constexpr int LDK = K + 4;  // even -> 8B alignment preserved
    constexpr int G = T / NP;
    constexpr int RPT = RPB / G;
    extern __shared__ float sm[];
    float* sW = sm;            // N * LDK
    float* sR = sm + N * LDK;  // RPB * K
    int tid = threadIdx.x;
    for (int i = tid; i < K * N; i += T) {
        int j = i / K, k = i - j * K;
        sW[j * LDK + k] = W[i];
    }
    int row0 = blockIdx.x * RPB;
    for (int i = tid; i < RPB * K; i += T) {
        int r = i / K, k = i - r * K;
        int row = row0 + r;
        float v = 0.f;
        if (row < nrows) {
            v = xin[(size_t)row * K + k];
            if (NSLICE > 0) {
#pragma unroll
                for (int s = 0; s < NSLICE; s++) v += part[((size_t)s * NN + row) * K + k];
            }
        }
        sR[i] = v;
    }
    __syncthreads();
    int j = tid % NP;
    int rg = tid / NP;
    if (j < N) {
        ull acc2[RPT];
#pragma unroll
        for (int t = 0; t < RPT; t++) acc2[t] = 0ull;
        const ull* wp = reinterpret_cast<const ull*>(&sW[j * LDK]);
        for (int k = 0; k < K; k += 4) {
            ull w01 = wp[k / 2];
            ull w23 = wp[k / 2 + 1];
#pragma unroll
            for (int t = 0; t < RPT; t++) {
                const ull* sp = reinterpret_cast<const ull*>(&sR[(rg + t * G) * K]);
                ffma2(acc2[t], w01, sp[k / 2]);
                ffma2(acc2[t], w23, sp[k / 2 + 1]);
            }
        }
        float bj = b[j];
#pragma unroll
        for (int t = 0; t < RPT; t++) {
            int row = row0 + rg + t * G;
            if (row < nrows) out[(size_t)row * N + j] = fmaxf(hsum2(acc2[t]) + bj, 0.f);
        }
    }
}

// c[k,j] = bih+bhh + sum_d q0[k,d]*(Wih[k,j,d] + Whh[k,j,d]); q0 computed inline from biases
__global__ void s2s_cvec(const float* __restrict__ Wih, const float* __restrict__ Whh,
                         const float* __restrict__ bih, const float* __restrict__ bhh,
                         float* __restrict__ c) {
    int k = blockIdx.y;
    int tid = threadIdx.x;
    int j = blockIdx.x * 256 + tid;
    __shared__ __align__(16) float sq[256];
    {
        const float* bi = bih + k * 1024;
        const float* bh = bhh + k * 1024;
        float gi = bi[tid] + bh[tid];
        float gg = bi[512 + tid] + bh[512 + tid];
        float go = bi[768 + tid] + bh[768 + tid];
        float cs = sigm(gi) * tanhf(gg);
        sq[tid] = sigm(go) * tanhf(cs);
    }
    __syncthreads();
    const float* wi = Wih + ((size_t)k * 1024 + j) * 512;
    const float* wh = Whh + ((size_t)k * 1024 + j) * 256;
    float acc = bih[k * 1024 + j] + bhh[k * 1024 + j];
    for (int d = 0; d < 256; d += 4) {
        float4 a = *reinterpret_cast<const float4*>(wi + d);
        float4 bq = *reinterpret_cast<const float4*>(wh + d);
        float4 s = *reinterpret_cast<const float4*>(&sq[d]);
        acc += (a.x + bq.x) * s.x + (a.y + bq.y) * s.y + (a.z + bq.z) * s.z + (a.w + bq.w) * s.w;
    }
    c[k * 1024 + j] = acc;
}

// ---------------- attention (fused gather + optional fused LSTM) ----------------
// PASS==0: query q0 computed inline from biases.
// PASS==1: q1 computed inline from gates + bias-derived cs0; q1 also written out.
template <int PASS>
__global__ void attn_kernel(const float* __restrict__ h4, const int* __restrict__ pn,
                            const float* __restrict__ gates, const float* __restrict__ bih,
                            const float* __restrict__ bhh, float* __restrict__ rout,
                            float* __restrict__ q1out) {
    int p = blockIdx.x, k = blockIdx.y;
    extern __shared__ float smdyn[];
    float* sx = smdyn;
    float* sq = smdyn + 64 * 256;
    float* dots = sq + 256;
    int* spn = (int*)(dots + 64);
    int tid = threadIdx.x;

    {
        const float* bi = bih + k * 1024;
        const float* bh = bhh + k * 1024;
        float bgi = bi[tid] + bh[tid];
        float bgg = bi[512 + tid] + bh[512 + tid];
        float bgo = bi[768 + tid] + bh[768 + tid];
        float cs0 = sigm(bgi) * tanhf(bgg);
        if (PASS == 0) {
            sq[tid] = sigm(bgo) * tanhf(cs0);
        } else {
            const float* g = gates + ((size_t)(k * P_PATH + p)) * 1024;
            float gi = g[tid], gf = g[256 + tid], gg = g[512 + tid], go = g[768 + tid];
            float cs = sigm(gf) * cs0 + sigm(gi) * tanhf(gg);
            float q = sigm(go) * tanhf(cs);
            sq[tid] = q;
            q1out[((size_t)k * P_PATH + p) * 256 + tid] = q;
        }
    }
    if (tid < 64) spn[tid] = pn[p * 64 + tid];
    __syncthreads();

    // gather x tile: 64 rows x 64 float4
    const float4* h4v = reinterpret_cast<const float4*>(h4);
    float4* sxv = reinterpret_cast<float4*>(sx);
    for (int i = tid; i < 64 * 64; i += 256) {
        int s = i >> 6, c = i & 63;
        sxv[i] = h4v[(size_t)spn[s] * 64 + c];
    }
    __syncthreads();

    int w = tid >> 5, lane = tid & 31;
    for (int s = w; s < 64; s += 8) {
        const float* xr = sx + s * 256;
        float part = 0.f;
#pragma unroll
        for (int m = 0; m < 8; m++) part += xr[lane + 32 * m] * sq[lane + 32 * m];
        for (int off = 16; off; off >>= 1) part += __shfl_down_sync(0xffffffffu, part, off);
        if (lane == 0) dots[s] = part;
    }
    __syncthreads();
    if (w == 0) {
        float a = dots[lane], b = dots[lane + 32];
        float mx = fmaxf(a, b);
        for (int off = 16; off; off >>= 1) mx = fmaxf(mx, __shfl_xor_sync(0xffffffffu, mx, off));
        float e0 = __expf(a - mx), e1 = __expf(b - mx);
        float sum = e0 + e1;
        for (int off = 16; off; off >>= 1) sum += __shfl_xor_sync(0xffffffffu, sum, off);
        float inv = 1.f / sum;
        dots[lane] = e0 * inv;
        dots[lane + 32] = e1 * inv;
    }
    __syncthreads();
    float acc = 0.f;
#pragma unroll 8
    for (int s = 0; s < 64; s++) acc += dots[s] * sx[s * 256 + tid];
    rout[((size_t)k * P_PATH + p) * 256 + tid] = acc;
}

// ---------------- gates1 = c[k,:] + r0 @ Wih[:, D:2D]^T  (f32x2, 32-row tiles) ----------------
__global__ void gates_gemm(const float* __restrict__ r0, const float* __restrict__ Wih,
                           const float* __restrict__ c, float* __restrict__ gates) {
    constexpr int RT = 32;
    int ct = blockIdx.x, rt = blockIdx.y, k = blockIdx.z;
    __shared__ __align__(16) float sR[RT * 256];
    int tid = threadIdx.x;
    const float* rbase = r0 + ((size_t)k * P_PATH + rt * RT) * 256;
    for (int i = tid; i < RT * 256; i += 256) sR[i] = rbase[i];
    __syncthreads();
    int j = ct * 256 + tid;
    const ull* wrow =
        reinterpret_cast<const ull*>(Wih + ((size_t)k * 1024 + j) * 512 + 256);
    ull acc2[RT];
#pragma unroll
    for (int r = 0; r < RT; r++) acc2[r] = 0ull;
    for (int d = 0; d < 256; d += 4) {
        ull w01 = wrow[d / 2];
        ull w23 = wrow[d / 2 + 1];
#pragma unroll
        for (int r = 0; r < RT; r++) {
            const ull* sp = reinterpret_cast<const ull*>(&sR[r * 256]);
            ffma2(acc2[r], w01, sp[d / 2]);
            ffma2(acc2[r], w23, sp[d / 2 + 1]);
        }
    }
    float cj = c[k * 1024 + j];
#pragma unroll
    for (int r = 0; r < RT; r++)
        gates[((size_t)k * P_PATH + rt * RT + r) * 1024 + j] = hsum2(acc2[r]) + cj;
}

// ---------------- xg[p] = bg + sum_k (q1_k . Wg_q + r1_k . Wg_r) ----------------
__global__ void xg_kernel(const float* __restrict__ q1, const float* __restrict__ r1,
                          const float* __restrict__ Wg, const float* __restrict__ bg,
                          float* __restrict__ xg) {
    int p = blockIdx.x, tid = threadIdx.x;
    float acc = 0.f;
#pragma unroll
    for (int k = 0; k < 3; k++) {
        acc += q1[((size_t)k * P_PATH + p) * 256 + tid] * Wg[k * 512 + tid];
        acc += r1[((size_t)k * P_PATH + p) * 256 + tid] * Wg[k * 512 + 256 + tid];
    }
    __shared__ float sred[8];
    for (int off = 16; off; off >>= 1) acc += __shfl_xor_sync(0xffffffffu, acc, off);
    if ((tid & 31) == 0) sred[tid >> 5] = acc;
    __syncthreads();
    if (tid == 0) {
        float t = 0.f;
#pragma unroll
        for (int i = 0; i < 8; i++) t += sred[i];
        xg[p] = t + bg[0];
    }
}

// ---------------- final MLP: [1,512] -> tanh 256 -> relu 64 -> sigmoid 1 ----------------
__global__ void final_kernel(const float* __restrict__ xg, const float* __restrict__ Wl1,
                             const float* __restrict__ bl1, const float* __restrict__ Wl2,
                             const float* __restrict__ bl2, const float* __restrict__ Wl3,
                             const float* __restrict__ bl3, float* __restrict__ out) {
    __shared__ __align__(16) float sxg[512];
    __shared__ __align__(16) float sz1[256];
    __shared__ float sz2[64];
    int tid = threadIdx.x;
    sxg[tid] = xg[tid];
    sxg[tid + 256] = xg[tid + 256];
    __syncthreads();
    {
        float a = bl1[tid];
        const float* w = Wl1 + (size_t)tid * 512;
        for (int p = 0; p < 512; p += 4) {
            float4 w4 = *reinterpret_cast<const float4*>(w + p);
            float4 x4 = *reinterpret_cast<const float4*>(&sxg[p]);
            a += w4.x * x4.x + w4.y * x4.y + w4.z * x4.z + w4.w * x4.w;
        }
        sz1[tid] = tanhf(a);
    }
    __syncthreads();
    if (tid < 64) {
        float bacc = bl2[tid];
        const float* w2 = Wl2 + (size_t)tid * 256;
        for (int hh = 0; hh < 256; hh += 4) {
            float4 w4 = *reinterpret_cast<const float4*>(w2 + hh);
            float4 z4 = *reinterpret_cast<const float4*>(&sz1[hh]);
            bacc += w4.x * z4.x + w4.y * z4.y + w4.z * z4.z + w4.w * z4.w;
        }
        sz2[tid] = fmaxf(bacc, 0.f);
    }
    __syncthreads();
    if (tid == 0) {
        float cacc = bl3[0];
        for (int j = 0; j < 64; j++) cacc += sz2[j] * Wl3[j];
        out[0] = 1.f / (1.f + __expf(-cacc));
    }
}

// ---------------- host launcher ----------------
extern "C" void kernel_launch(void* const* d_in, const int* in_sizes, int n_in,
                              void* d_out, int out_size) {
    const float* h = (const float*)d_in[0];
    const int* src = (const int*)d_in[1];
    const int* dst = (const int*)d_in[2];
    const int* pn = (const int*)d_in[3];
    const float* W1 = (const float*)d_in[4];
    const float* b1 = (const float*)d_in[5];
    const float* W2 = (const float*)d_in[6];
    const float* b2 = (const float*)d_in[7];
    const float* W3 = (const float*)d_in[8];
    const float* b3 = (const float*)d_in[9];
    const float* W4 = (const float*)d_in[10];
    const float* b4 = (const float*)d_in[11];
    const float* Wih = (const float*)d_in[12];
    const float* Whh = (const float*)d_in[13];
    const float* bih = (const float*)d_in[14];
    const float* bhh = (const float*)d_in[15];
    const float* Wg = (const float*)d_in[16];
    const float* bg = (const float*)d_in[17];
    const float* Wl1 = (const float*)d_in[18];
    const float* bl1 = (const float*)d_in[19];
    const float* Wl2 = (const float*)d_in[20];
    const float* bl2 = (const float*)d_in[21];
    const float* Wl3 = (const float*)d_in[22];
    const float* bl3 = (const float*)d_in[23];
    int E = in_sizes[1];
    float* out = (float*)d_out;

    float *agg, *part, *h1, *h2, *h3, *h4, *cvec, *r0, *gates, *q1, *r1, *xg;
    int *deg, *off, *cur, *srcs;
    cudaGetSymbolAddress((void**)&agg, g_agg);
    cudaGetSymbolAddress((void**)&part, g_part);
    cudaGetSymbolAddress((void**)&h1, g_h1);
    cudaGetSymbolAddress((void**)&h2, g_h2);
    cudaGetSymbolAddress((void**)&h3, g_h3);
    cudaGetSymbolAddress((void**)&h4, g_h4);
    cudaGetSymbolAddress((void**)&cvec, g_c);
    cudaGetSymbolAddress((void**)&r0, g_r0);
    cudaGetSymbolAddress((void**)&gates, g_gates);
    cudaGetSymbolAddress((void**)&q1, g_q1);
    cudaGetSymbolAddress((void**)&r1, g_r1);
    cudaGetSymbolAddress((void**)&xg, g_xg);
    cudaGetSymbolAddress((void**)&deg, g_deg);
    cudaGetSymbolAddress((void**)&off, g_off);
    cudaGetSymbolAddress((void**)&cur, g_cur);
    cudaGetSymbolAddress((void**)&srcs, g_srcs);

    // smem for gemm_relu<K,N,..,RPB>: (N*(K+4) + RPB*K) * 4 bytes
    const int smem1 = (24 * 12 + 32 * 8) * 4;
    const int smem2 = (64 * 28 + 32 * 24) * 4;
    const int smem3 = (128 * 68 + 64 * 64) * 4;
    const int smem4 = (256 * 132 + 64 * 128) * 4;  // ~168 KB
    cudaFuncSetAttribute(gemm_relu<64, 128, 128, 512, 64, 0>,
                         cudaFuncAttributeMaxDynamicSharedMemorySize, smem3);
    cudaFuncSetAttribute(gemm_relu<128, 256, 256, 512, 64, 0>,
                         cudaFuncAttributeMaxDynamicSharedMemorySize, smem4);
    const int attn_smem = (64 * 256 + 256 + 64 + 64) * 4;
    cudaFuncSetAttribute(attn_kernel<0>, cudaFuncAttributeMaxDynamicSharedMemorySize, attn_smem);
    cudaFuncSetAttribute(attn_kernel<1>, cudaFuncAttributeMaxDynamicSharedMemorySize, attn_smem);

    // ---- CSR build ----
    cudaMemsetAsync(deg, 0, NN * sizeof(int));
    hist_kernel<<<(E + 255) / 256, 256>>>(dst, deg, E);
    scan_kernel<<<1, 1024>>>(deg, off, cur);
    bucket_kernel<<<(E + 255) / 256, 256>>>(src, dst, cur, srcs, E);

    // ---- 4 GIN layers ----
    aggregate_sliced<8, 8><<<(NN * 2 * 8 + 255) / 256, 256>>>(h, off, srcs, part);
    gemm_relu<8, 24, 32, 256, 32, 8><<<(NN + 31) / 32, 256, smem1>>>(h, part, W1, b1, h1, NN);

    aggregate_sliced<24, 4><<<(NN * 6 * 4 + 255) / 256, 256>>>(h1, off, srcs, part);
    gemm_relu<24, 64, 64, 256, 32, 4><<<(NN + 31) / 32, 256, smem2>>>(h1, part, W2, b2, h2, NN);

    aggregate_k<64><<<(NN * 16 + 255) / 256, 256>>>(h2, off, srcs, agg);
    gemm_relu<64, 128, 128, 512, 64, 0><<<(NN + 63) / 64, 512, smem3>>>(agg, nullptr, W3, b3,
                                                                        h3, NN);

    aggregate_k<128><<<(NN * 32 + 255) / 256, 256>>>(h3, off, srcs, agg);
    gemm_relu<128, 256, 256, 512, 64, 0><<<(NN + 63) / 64, 512, smem4>>>(agg, nullptr, W4, b4,
                                                                         h4, NN);

    // ---- Set2Set (3 modules batched via grid.y) ----
    attn_kernel<0><<<dim3(P_PATH, 3), 256, attn_smem>>>(h4, pn, nullptr, bih, bhh, r0, nullptr);
    s2s_cvec<<<dim3(4, 3), 256>>>(Wih, Whh, bih, bhh, cvec);
    gates_gemm<<<dim3(4, P_PATH / 32, 3), 256>>>(r0, Wih, cvec, gates);
    attn_kernel<1><<<dim3(P_PATH, 3), 256, attn_smem>>>(h4, pn, gates, bih, bhh, r1, q1);

    xg_kernel<<<P_PATH, 256>>>(q1, r1, Wg, bg, xg);
    final_kernel<<<1, 256>>>(xg, Wl1, bl1, Wl2, bl2, Wl3, bl3, out);
}